// round 15
// baseline (speedup 1.0000x reference)
#include <cuda_runtime.h>

// Shapes (fixed by the problem)
#define BB 64
#define NN 21
#define HH 128
#define WW 128
// Total float4 = 5,505,024 = 128 * 43,008  (exact — no scalar tail)

static constexpr int GRID    = 592;   // 148 SMs * 4 — wave-even
static constexpr int THREADS = 256;
static constexpr int UNROLL  = 4;     // 8 float4 in flight = 32 data regs: fits 64-reg clamp
static constexpr int CHUNK   = 32 * UNROLL;            // 128 float4 per warp-chunk (2KB)
static constexpr int NCHUNKS = 5505024 / CHUNK;        // 43,008
static constexpr int TOTAL_WARPS = GRID * (THREADS / 32);  // 4736
static constexpr int NKP = BB * NN;   // 1344 keypoints

__device__ float2 g_part[GRID];       // (mse, pck) partials
__device__ unsigned int g_done_ctr;   // zero-init at load; reset by last block

__device__ __forceinline__ float warp_sum(float v) {
    #pragma unroll
    for (int off = 16; off > 0; off >>= 1)
        v += __shfl_down_sync(0xFFFFFFFFu, v, off);
    return v;
}

__device__ __forceinline__ float sqdiff4(float4 a, float4 b, float acc) {
    float d;
    d = a.x - b.x; acc = fmaf(d, d, acc);
    d = a.y - b.y; acc = fmaf(d, d, acc);
    d = a.z - b.z; acc = fmaf(d, d, acc);
    d = a.w - b.w; acc = fmaf(d, d, acc);
    return acc;
}

__global__ void __launch_bounds__(THREADS, 4) fused_loss_kernel(
    const float4* __restrict__ pred4,
    const float4* __restrict__ gt4,
    const float*  __restrict__ pred,   // scalar view for gathers
    const float*  __restrict__ kp,     // (B, N, 2) -> [x, y]
    float* __restrict__ out)
{
    const int lane = threadIdx.x & 31;
    const int gw   = blockIdx.x * (THREADS / 32) + (threadIdx.x >> 5);  // global warp id

    // ---- streaming MSE over warp-contiguous 2KB chunks ----
    // All 8 loads of a batch fit the register budget -> truly front-batched in SASS.
    float acc[UNROLL];
    #pragma unroll
    for (int u = 0; u < UNROLL; u++) acc[u] = 0.0f;

    #pragma unroll 1
    for (int c = gw; c < NCHUNKS; c += TOTAL_WARPS) {
        const float4* pa = pred4 + c * CHUNK + lane;
        const float4* pb = gt4   + c * CHUNK + lane;
        float4 a[UNROLL], b[UNROLL];
        #pragma unroll
        for (int u = 0; u < UNROLL; u++) a[u] = pa[u * 32];
        #pragma unroll
        for (int u = 0; u < UNROLL; u++) b[u] = pb[u * 32];
        #pragma unroll
        for (int u = 0; u < UNROLL; u++) acc[u] = sqdiff4(a[u], b[u], acc[u]);
    }
    float mse_acc = (acc[0] + acc[1]) + (acc[2] + acc[3]);

    // ---- keypoint gather (first NKP threads) ----
    const int tid_global = blockIdx.x * THREADS + threadIdx.x;
    float pck_acc = 0.0f;
    if (tid_global < NKP) {
        float2 xy = *(const float2*)&kp[2 * tid_global];
        int x = (int)fminf(fmaxf(xy.x, 0.0f), (float)(WW - 1));
        int y = (int)fminf(fmaxf(xy.y, 0.0f), (float)(HH - 1));
        float v = pred[(tid_global * HH + y) * WW + x];
        float e = 1.0f - v;
        pck_acc = e * e;
    }

    // ---- block reduction of both accumulators ----
    __shared__ float s1[THREADS / 32];
    __shared__ float s2[THREADS / 32];
    int wid = threadIdx.x >> 5;
    float m = warp_sum(mse_acc);
    float p = warp_sum(pck_acc);
    if (lane == 0) { s1[wid] = m; s2[wid] = p; }
    __syncthreads();

    __shared__ bool s_is_last;
    if (wid == 0) {
        float mm = (lane < THREADS / 32) ? s1[lane] : 0.0f;
        float pp = (lane < THREADS / 32) ? s2[lane] : 0.0f;
        mm = warp_sum(mm);
        pp = warp_sum(pp);
        if (lane == 0) {
            g_part[blockIdx.x] = make_float2(mm, pp);
            __threadfence();
            unsigned int prev = atomicAdd(&g_done_ctr, 1u);
            s_is_last = (prev == (unsigned int)(gridDim.x - 1));
        }
    }
    __syncthreads();

    // ---- last block finalizes ----
    if (s_is_last) {
        float ma = 0.0f, pa = 0.0f;
        for (int j = threadIdx.x; j < GRID; j += THREADS) {
            float2 v = g_part[j];
            ma += v.x;
            pa += v.y;
        }
        float mw = warp_sum(ma);
        float pw = warp_sum(pa);
        if (lane == 0) { s1[wid] = mw; s2[wid] = pw; }
        __syncthreads();
        if (wid == 0) {
            float mm = (lane < THREADS / 32) ? s1[lane] : 0.0f;
            float pp = (lane < THREADS / 32) ? s2[lane] : 0.0f;
            mm = warp_sum(mm);
            pp = warp_sum(pp);
            if (lane == 0) {
                float mse = mm / (float)((long long)BB * NN * HH * WW);
                float pck = pp / (float)NKP;
                out[0] = mse + pck;   // total (weights are 1.0)
                out[1] = mse;
                out[2] = pck;
                g_done_ctr = 0;       // reset for next graph replay
            }
        }
    }
}

extern "C" void kernel_launch(void* const* d_in, const int* in_sizes, int n_in,
                              void* d_out, int out_size)
{
    const float* pred = (const float*)d_in[0];
    const float* gt   = (const float*)d_in[1];
    const float* kp   = (const float*)d_in[2];
    float* out = (float*)d_out;

    fused_loss_kernel<<<GRID, THREADS>>>(
        (const float4*)pred, (const float4*)gt, pred, kp, out);
}

// round 16
// speedup vs baseline: 1.0533x; 1.0533x over previous
#include <cuda_runtime.h>

// Shapes (fixed by the problem)
#define BB 64
#define NN 21
#define HH 128
#define WW 128
// Total float4 = 5,505,024 = 192 * 28,672  (exact — no scalar tail)

static constexpr int GRID    = 592;   // 148 SMs * 4 — wave-even
static constexpr int THREADS = 256;
static constexpr int UNROLL  = 6;
static constexpr int CHUNK   = 32 * UNROLL;            // 192 float4 per warp-chunk (3KB)
static constexpr int NCHUNKS = 5505024 / CHUNK;        // 28,672
static constexpr int TOTAL_WARPS = GRID * (THREADS / 32);  // 4736
static constexpr int NKP = BB * NN;   // 1344 keypoints

__device__ float2 g_part[GRID];       // (mse, pck) partials
__device__ unsigned int g_done_ctr;   // zero-init at load; reset by last block

__device__ __forceinline__ float warp_sum(float v) {
    #pragma unroll
    for (int off = 16; off > 0; off >>= 1)
        v += __shfl_down_sync(0xFFFFFFFFu, v, off);
    return v;
}

__device__ __forceinline__ float sqdiff4(float4 a, float4 b, float acc) {
    float d;
    d = a.x - b.x; acc = fmaf(d, d, acc);
    d = a.y - b.y; acc = fmaf(d, d, acc);
    d = a.z - b.z; acc = fmaf(d, d, acc);
    d = a.w - b.w; acc = fmaf(d, d, acc);
    return acc;
}

__global__ void __launch_bounds__(THREADS, 4) fused_loss_kernel(
    const float4* __restrict__ pred4,
    const float4* __restrict__ gt4,
    const float*  __restrict__ pred,   // scalar view for gathers
    const float*  __restrict__ kp,     // (B, N, 2) -> [x, y]
    float* __restrict__ out)
{
    const int lane = threadIdx.x & 31;
    const int gw   = blockIdx.x * (THREADS / 32) + (threadIdx.x >> 5);  // global warp id

    // ---- streaming MSE over warp-contiguous 3KB chunks ----
    // Warp's 6 loads walk one contiguous 3KB span per array -> DRAM row streaks.
    float acc[UNROLL];
    #pragma unroll
    for (int u = 0; u < UNROLL; u++) acc[u] = 0.0f;

    #pragma unroll 1
    for (int c = gw; c < NCHUNKS; c += TOTAL_WARPS) {
        const float4* pa = pred4 + c * CHUNK + lane;
        const float4* pb = gt4   + c * CHUNK + lane;
        float4 a[UNROLL], b[UNROLL];
        #pragma unroll
        for (int u = 0; u < UNROLL; u++) a[u] = pa[u * 32];
        #pragma unroll
        for (int u = 0; u < UNROLL; u++) b[u] = pb[u * 32];
        #pragma unroll
        for (int u = 0; u < UNROLL; u++) acc[u] = sqdiff4(a[u], b[u], acc[u]);
    }
    float mse_acc = ((acc[0] + acc[1]) + (acc[2] + acc[3])) + (acc[4] + acc[5]);

    // ---- keypoint gather (first NKP threads) ----
    const int tid_global = blockIdx.x * THREADS + threadIdx.x;
    float pck_acc = 0.0f;
    if (tid_global < NKP) {
        float2 xy = *(const float2*)&kp[2 * tid_global];
        int x = (int)fminf(fmaxf(xy.x, 0.0f), (float)(WW - 1));
        int y = (int)fminf(fmaxf(xy.y, 0.0f), (float)(HH - 1));
        float v = pred[(tid_global * HH + y) * WW + x];
        float e = 1.0f - v;
        pck_acc = e * e;
    }

    // ---- block reduction of both accumulators ----
    __shared__ float s1[THREADS / 32];
    __shared__ float s2[THREADS / 32];
    int wid = threadIdx.x >> 5;
    float m = warp_sum(mse_acc);
    float p = warp_sum(pck_acc);
    if (lane == 0) { s1[wid] = m; s2[wid] = p; }
    __syncthreads();

    __shared__ bool s_is_last;
    if (wid == 0) {
        float mm = (lane < THREADS / 32) ? s1[lane] : 0.0f;
        float pp = (lane < THREADS / 32) ? s2[lane] : 0.0f;
        mm = warp_sum(mm);
        pp = warp_sum(pp);
        if (lane == 0) {
            g_part[blockIdx.x] = make_float2(mm, pp);
            __threadfence();
            unsigned int prev = atomicAdd(&g_done_ctr, 1u);
            s_is_last = (prev == (unsigned int)(gridDim.x - 1));
        }
    }
    __syncthreads();

    // ---- last block finalizes ----
    if (s_is_last) {
        float ma = 0.0f, pa = 0.0f;
        for (int j = threadIdx.x; j < GRID; j += THREADS) {
            float2 v = g_part[j];
            ma += v.x;
            pa += v.y;
        }
        float mw = warp_sum(ma);
        float pw = warp_sum(pa);
        if (lane == 0) { s1[wid] = mw; s2[wid] = pw; }
        __syncthreads();
        if (wid == 0) {
            float mm = (lane < THREADS / 32) ? s1[lane] : 0.0f;
            float pp = (lane < THREADS / 32) ? s2[lane] : 0.0f;
            mm = warp_sum(mm);
            pp = warp_sum(pp);
            if (lane == 0) {
                float mse = mm / (float)((long long)BB * NN * HH * WW);
                float pck = pp / (float)NKP;
                out[0] = mse + pck;   // total (weights are 1.0)
                out[1] = mse;
                out[2] = pck;
                g_done_ctr = 0;       // reset for next graph replay
            }
        }
    }
}

extern "C" void kernel_launch(void* const* d_in, const int* in_sizes, int n_in,
                              void* d_out, int out_size)
{
    const float* pred = (const float*)d_in[0];
    const float* gt   = (const float*)d_in[1];
    const float* kp   = (const float*)d_in[2];
    float* out = (float*)d_out;

    fused_loss_kernel<<<GRID, THREADS>>>(
        (const float4*)pred, (const float4*)gt, pred, kp, out);
}